// round 17
// baseline (speedup 1.0000x reference)
#include <cuda_runtime.h>

// SDF_75806172774865 — float2 k-pair mapping: lane l owns k=(2l,2l+1) of ONE
// point, loading 3x float2 from v, 3x from vn, 1x from sr (7 LDG.64/point
// vs previous 14 LDG.32) -> ~2.2x fewer L1 wavefronts on the same stream.
// Fused acq_rel ticket finalize (no CCTL.IVALL).
// points: (N,P,3) f32; v,vn: (N,P,K,3) f32; sr: (N,P,K) f32; out: (N,) f32

#define WPB 16
#define TPB (WPB * 32)

__device__ float        g_scratch[2];  // zero-init at module load
__device__ unsigned int g_ticket;      // zero-init at module load

__device__ __forceinline__ unsigned ticket_inc_acq_rel() {
    unsigned t;
    asm volatile("atom.acq_rel.gpu.add.u32 %0, [%1], 1;"
                 : "=r"(t) : "l"(&g_ticket) : "memory");
    return t;
}

__global__ void sdf_init_out(float* out, int n) {   // fallback path only
    int i = threadIdx.x;
    if (i < n) out[i] = 0.0f;
}

__global__ __launch_bounds__(TPB)
void sdf_f2_60(const float* __restrict__ points,
               const float* __restrict__ v,
               const float* __restrict__ vn,
               const float* __restrict__ sr,
               float* __restrict__ out,
               int total_pts,   // N*P
               int P,
               int nblocks)
{
    __shared__ float s_acc[2];
    const int tid  = threadIdx.x;
    if (tid < 2) s_acc[tid] = 0.0f;
    __syncthreads();

    const int warp = tid >> 5;
    const int lane = tid & 31;
    const int pt   = blockIdx.x * WPB + warp;

    if (pt < total_pts) {
        const float* pp = points + (size_t)pt * 3;
        const float px = pp[0], py = pp[1], pz = pp[2];

        // rows are 16B-aligned: v/vn rows are 180 floats (720B), sr 60 floats
        const float2* v2  = (const float2*)(v  + (size_t)pt * 180);
        const float2* vn2 = (const float2*)(vn + (size_t)pt * 180);
        const float2* sr2 = (const float2*)(sr + (size_t)pt * 60);

        float num = 0.0f, den = 0.0f;

        const bool active = lane < 30;        // 30 lanes x 2 k = 60
        if (active) {
            const int i3 = lane * 3;
            // ---- 7 x LDG.64, front-batched ----
            const float2 va = v2[i3 + 0];     // v[k0].x, v[k0].y
            const float2 vb = v2[i3 + 1];     // v[k0].z, v[k1].x
            const float2 vc = v2[i3 + 2];     // v[k1].y, v[k1].z
            const float2 na = vn2[i3 + 0];
            const float2 nb = vn2[i3 + 1];
            const float2 nc = vn2[i3 + 2];
            const float2 rr = sr2[lane];      // sr[k0], sr[k1]

            // ---- k0 = 2*lane ----
            {
                const float dx = px - va.x, dy = py - va.y, dz = pz - vb.x;
                const float d  = dx * dx + dy * dy + dz * dz;
                const float w  = 1.0f - __fdividef(d, rr.x);
                const float w2 = w * w;
                const float phi = (d < rr.x) ? (w2 * w2) : 1e-18f;
                const float dot = na.x * dx + na.y * dy + nb.x * dz;
                num = fmaf(phi, dot, num);
                den += phi;
            }
            // ---- k1 = 2*lane + 1 ----
            {
                const float dx = px - vb.y, dy = py - vc.x, dz = pz - vc.y;
                const float d  = dx * dx + dy * dy + dz * dz;
                const float w  = 1.0f - __fdividef(d, rr.y);
                const float w2 = w * w;
                const float phi = (d < rr.y) ? (w2 * w2) : 1e-18f;
                const float dot = nb.y * dx + nc.x * dy + nc.y * dz;
                num = fmaf(phi, dot, num);
                den += phi;
            }
        }

        #pragma unroll
        for (int off = 16; off > 0; off >>= 1) {
            num += __shfl_xor_sync(0xffffffffu, num, off);
            den += __shfl_xor_sync(0xffffffffu, den, off);
        }

        if (lane == 0) {
            const float sdf = __fdividef(num, den);
            atomicAdd(&s_acc[pt / P], sdf * sdf);
        }
    }

    __syncthreads();

    // ---- finalize: scratch atomics + acq_rel ticket; last block writes out.
    if (tid == 0) {
        const float v0 = s_acc[0];
        const float v1 = s_acc[1];
        if (v0 != 0.0f) atomicAdd(&g_scratch[0], v0);
        if (v1 != 0.0f) atomicAdd(&g_scratch[1], v1);
        const unsigned t = ticket_inc_acq_rel();
        if (t == (unsigned)(nblocks - 1)) {
            out[0] = atomicExch(&g_scratch[0], 0.0f);
            out[1] = atomicExch(&g_scratch[1], 0.0f);
            atomicExch(&g_ticket, 0u);   // reset for next graph replay
        }
    }
}

// ---- generic fallback (any K / N / shape) ----
#define FB_WARPS 16
__global__ __launch_bounds__(FB_WARPS * 32)
void sdf_kernel_generic(const float* __restrict__ points,
                        const float* __restrict__ v,
                        const float* __restrict__ vn,
                        const float* __restrict__ sr,
                        float* __restrict__ out,
                        int total_pts, int P, int K)
{
    __shared__ float s_acc[2];
    const int tid  = threadIdx.x;
    if (tid < 2) s_acc[tid] = 0.0f;
    __syncthreads();

    const int warp = tid >> 5;
    const int lane = tid & 31;
    const int pt   = blockIdx.x * FB_WARPS + warp;

    if (pt < total_pts) {
        const float* pp = points + (size_t)pt * 3;
        const float px = pp[0], py = pp[1], pz = pp[2];
        const float* vb  = v  + (size_t)pt * K * 3;
        const float* vnb = vn + (size_t)pt * K * 3;
        const float* srb = sr + (size_t)pt * K;

        float num = 0.0f, den = 0.0f;
        for (int k = lane; k < K; k += 32) {
            const int b = k * 3;
            const float dx = px - vb[b + 0];
            const float dy = py - vb[b + 1];
            const float dz = pz - vb[b + 2];
            const float d  = dx * dx + dy * dy + dz * dz;
            const float r  = srb[k];
            const float w  = 1.0f - d / r;
            const float w2 = w * w;
            const float phi = (d < r) ? (w2 * w2) : 1e-18f;
            const float dot = vnb[b + 0] * dx + vnb[b + 1] * dy + vnb[b + 2] * dz;
            num = fmaf(phi, dot, num);
            den += phi;
        }
        #pragma unroll
        for (int off = 16; off > 0; off >>= 1) {
            num += __shfl_xor_sync(0xffffffffu, num, off);
            den += __shfl_xor_sync(0xffffffffu, den, off);
        }
        if (lane == 0) {
            const float sdf = num / den;
            atomicAdd(&s_acc[pt / P], sdf * sdf);
        }
    }
    __syncthreads();
    if (tid < 2) {
        const float val = s_acc[tid];
        if (val != 0.0f) atomicAdd(&out[tid], val);
    }
}

extern "C" void kernel_launch(void* const* d_in, const int* in_sizes, int n_in,
                              void* d_out, int out_size)
{
    const float* points = (const float*)d_in[0];
    const float* v      = (const float*)d_in[1];
    const float* vn     = (const float*)d_in[2];
    const float* sr     = (const float*)d_in[3];
    float* out          = (float*)d_out;

    const int total_pts = in_sizes[0] / 3;          // N*P
    const int N         = out_size;                 // 2
    const int P         = total_pts / N;            // 100000
    const int K         = in_sizes[3] / total_pts;  // 60

    if (K == 60 && N == 2) {
        const int blocks = (total_pts + WPB - 1) / WPB;
        sdf_f2_60<<<blocks, TPB>>>(points, v, vn, sr, out,
                                   total_pts, P, blocks);
    } else {
        sdf_init_out<<<1, 32>>>(out, N);
        const int blocks = (total_pts + FB_WARPS - 1) / FB_WARPS;
        sdf_kernel_generic<<<blocks, FB_WARPS * 32>>>(points, v, vn, sr, out,
                                                      total_pts, P, K);
    }
}